// round 2
// baseline (speedup 1.0000x reference)
#include <cuda_runtime.h>
#include <math.h>

#define D      128
#define D4     32
#define NE_MAX 100000
#define EPW    4

// Scratch (no allocation allowed) — 3 x 51.2 MB
__device__ float g_h[NE_MAX * D];
__device__ float g_agg[NE_MAX * D];
__device__ float g_hcur[NE_MAX * D];

// ---------------- Phase A: L2-normalize + zero accumulator ----------------
__global__ void norm_zero_kernel(const float4* __restrict__ ent, int rows) {
    int gw   = (blockIdx.x * blockDim.x + threadIdx.x) >> 5;
    int lane = threadIdx.x & 31;
    if (gw >= rows) return;
    float4 v = ent[gw * D4 + lane];
    float  s = v.x * v.x + v.y * v.y + v.z * v.z + v.w * v.w;
#pragma unroll
    for (int o = 16; o > 0; o >>= 1) s += __shfl_xor_sync(0xffffffffu, s, o);
    float inv = 1.0f / fmaxf(sqrtf(s), 1e-12f);
    ((float4*)g_h)[gw * D4 + lane]   = make_float4(v.x * inv, v.y * inv, v.z * inv, v.w * inv);
    ((float4*)g_agg)[gw * D4 + lane] = make_float4(0.f, 0.f, 0.f, 0.f);
}

// ---------------- Phase B: edge gather + scale + scatter-add ----------------
// agg[d] += edge_norm * (h[src] + rel[etype]);  one warp per edge, float4/lane.
__global__ void edge_kernel(const float4* __restrict__ rel,
                            const float* __restrict__ enorm,
                            const int*   __restrict__ src,
                            const int*   __restrict__ dst,
                            const int*   __restrict__ et,
                            int nE) {
    int gw   = (blockIdx.x * blockDim.x + threadIdx.x) >> 5;
    int lane = threadIdx.x & 31;
    const float4* h4 = (const float4*)g_h;
    int e0 = gw * EPW;
#pragma unroll
    for (int i = 0; i < EPW; ++i) {
        int e = e0 + i;
        if (e < nE) {
            int   s  = __ldg(src + e);
            int   d  = __ldg(dst + e);
            int   t  = __ldg(et + e);
            float nm = __ldg(enorm + e);
            float4 hv = h4[s * D4 + lane];
            float4 rv = rel[t * D4 + lane];
            float4 v  = make_float4((hv.x + rv.x) * nm, (hv.y + rv.y) * nm,
                                    (hv.z + rv.z) * nm, (hv.w + rv.w) * nm);
            float* p = g_agg + (d * D + lane * 4);
            asm volatile("red.global.add.v4.f32 [%0], {%1, %2, %3, %4};"
                         :: "l"(p), "f"(v.x), "f"(v.y), "f"(v.z), "f"(v.w)
                         : "memory");
        }
    }
}

// ---------------- Phase C: node GEMMs with fused epilogues ----------------
// EPI==0: g_hcur = rrelu(g_agg @ B0 + g_h @ B1)                 (K = 256, 2 segs)
// EPI==1: out    = gate*g_hcur + (1-gate)*his,
//         gate = sigmoid(g_hcur @ B0 + bias)                    (K = 128, 1 seg)
template <int EPI>
__global__ __launch_bounds__(256, 2)
void gemm_kernel(const float* __restrict__ B0, const float* __restrict__ B1,
                 const float* __restrict__ bias, const float* __restrict__ his,
                 float* __restrict__ out, int M) {
    __shared__ float As[8][132];
    __shared__ float Bs[8][128];

    const int tid = threadIdx.x;
    const int m0  = blockIdx.x * 128;
    const int tx  = tid & 15;
    const int ty  = tid >> 4;

    float acc[8][8];
#pragma unroll
    for (int i = 0; i < 8; i++)
#pragma unroll
        for (int j = 0; j < 8; j++) acc[i][j] = 0.f;

    const int aRow = tid >> 1;
    const int aCol = (tid & 1) * 4;
    const int bRow = tid >> 5;
    const int bCol = (tid & 31) * 4;
    const bool aValid = (m0 + aRow) < M;

    const int NSEG = (EPI == 0) ? 2 : 1;
    for (int seg = 0; seg < NSEG; ++seg) {
        const float* A = (EPI == 0) ? (seg ? g_h : g_agg) : g_hcur;
        const float* B = seg ? B1 : B0;
        for (int k0 = 0; k0 < 128; k0 += 8) {
            float4 av = make_float4(0.f, 0.f, 0.f, 0.f);
            if (aValid) av = *(const float4*)(A + (m0 + aRow) * 128 + k0 + aCol);
            float4 bv = *(const float4*)(B + (k0 + bRow) * 128 + bCol);
            __syncthreads();
            As[aCol + 0][aRow] = av.x;
            As[aCol + 1][aRow] = av.y;
            As[aCol + 2][aRow] = av.z;
            As[aCol + 3][aRow] = av.w;
            *(float4*)(&Bs[bRow][bCol]) = bv;
            __syncthreads();
#pragma unroll
            for (int k = 0; k < 8; k++) {
                float a[8], b[8];
#pragma unroll
                for (int i = 0; i < 8; i++) a[i] = As[k][ty * 8 + i];
#pragma unroll
                for (int j = 0; j < 8; j++) b[j] = Bs[k][tx * 8 + j];
#pragma unroll
                for (int i = 0; i < 8; i++)
#pragma unroll
                    for (int j = 0; j < 8; j++)
                        acc[i][j] = fmaf(a[i], b[j], acc[i][j]);
            }
        }
    }

    const int colb = tx * 8;
    if (EPI == 0) {
        const float SLOPE = 0.22916666666666666f;  // eval-mode rrelu mean slope
#pragma unroll
        for (int i = 0; i < 8; i++) {
            int r = m0 + ty * 8 + i;
            if (r >= M) continue;
            float v[8];
#pragma unroll
            for (int j = 0; j < 8; j++) {
                float c = acc[i][j];
                v[j] = (c >= 0.f) ? c : SLOPE * c;
            }
            float4* o = (float4*)(g_hcur + r * 128 + colb);
            o[0] = make_float4(v[0], v[1], v[2], v[3]);
            o[1] = make_float4(v[4], v[5], v[6], v[7]);
        }
    } else {
        float bj[8];
#pragma unroll
        for (int j = 0; j < 8; j++) bj[j] = bias[colb + j];
#pragma unroll
        for (int i = 0; i < 8; i++) {
            int r = m0 + ty * 8 + i;
            if (r >= M) continue;
            const float4* hc4 = (const float4*)(g_hcur + r * 128 + colb);
            const float4* hi4 = (const float4*)(his + r * 128 + colb);
            float4 hcA = hc4[0], hcB = hc4[1];
            float4 hiA = hi4[0], hiB = hi4[1];
            float hc[8] = {hcA.x, hcA.y, hcA.z, hcA.w, hcB.x, hcB.y, hcB.z, hcB.w};
            float hi[8] = {hiA.x, hiA.y, hiA.z, hiA.w, hiB.x, hiB.y, hiB.z, hiB.w};
            float v[8];
#pragma unroll
            for (int j = 0; j < 8; j++) {
                float z = acc[i][j] + bj[j];
                float g = 1.f / (1.f + __expf(-z));
                v[j] = g * hc[j] + (1.f - g) * hi[j];
            }
            float4* o = (float4*)(out + r * 128 + colb);
            o[0] = make_float4(v[0], v[1], v[2], v[3]);
            o[1] = make_float4(v[4], v[5], v[6], v[7]);
        }
    }
}

extern "C" void kernel_launch(void* const* d_in, const int* in_sizes, int n_in,
                              void* d_out, int out_size) {
    const float* ent = (const float*)d_in[0];
    const float* rel = (const float*)d_in[1];
    const float* his = (const float*)d_in[2];
    const float* Wn  = (const float*)d_in[3];
    const float* Ws  = (const float*)d_in[4];
    const float* Wt  = (const float*)d_in[5];
    const float* tb  = (const float*)d_in[6];
    const float* en  = (const float*)d_in[7];
    const int*   src = (const int*)d_in[8];
    const int*   dst = (const int*)d_in[9];
    const int*   et  = (const int*)d_in[10];

    int M = in_sizes[0] / D;   // 100000
    int E = in_sizes[7];       // 2000000

    // Phase A: normalize + zero agg (1 warp / row)
    int nblocks = (M + 7) / 8;
    norm_zero_kernel<<<nblocks, 256>>>((const float4*)ent, M);

    // Phase B: edges (1 warp / edge, EPW edges per warp)
    int ewarps  = (E + EPW - 1) / EPW;
    int eblocks = (ewarps + 7) / 8;
    edge_kernel<<<eblocks, 256>>>((const float4*)rel, en, src, dst, et, E);

    // Phase C: node GEMMs
    int gblocks = (M + 127) / 128;
    gemm_kernel<0><<<gblocks, 256>>>(Wn, Ws, nullptr, nullptr, nullptr, M);
    gemm_kernel<1><<<gblocks, 256>>>(Wt, nullptr, tb, his, (float*)d_out, M);
}

// round 3
// speedup vs baseline: 1.0197x; 1.0197x over previous
#include <cuda_runtime.h>
#include <cuda_fp16.h>
#include <math.h>

#define D      128
#define D4     32
#define NE_MAX 100000
#define NREL   1000
#define EPW    4

// Scratch (no allocation allowed)
__device__ float  g_h[NE_MAX * D];        // 51.2 MB fp32 normalized h (GEMM A)
__device__ float  g_agg[NE_MAX * D];      // 51.2 MB accumulator
__device__ __half g_h16[NE_MAX * D];      // 25.6 MB fp16 copy for edge gather
__device__ __half g_rel16[NREL * D];      // 256 KB fp16 rel table

// ---------------- Phase A: L2-normalize + zero accumulator + fp16 copy ----------------
__global__ void norm_zero_kernel(const float4* __restrict__ ent, int rows) {
    int gw   = (blockIdx.x * blockDim.x + threadIdx.x) >> 5;
    int lane = threadIdx.x & 31;
    if (gw >= rows) return;
    float4 v = ent[gw * D4 + lane];
    float  s = v.x * v.x + v.y * v.y + v.z * v.z + v.w * v.w;
#pragma unroll
    for (int o = 16; o > 0; o >>= 1) s += __shfl_xor_sync(0xffffffffu, s, o);
    float inv = 1.0f / fmaxf(sqrtf(s), 1e-12f);
    float4 hv = make_float4(v.x * inv, v.y * inv, v.z * inv, v.w * inv);
    ((float4*)g_h)[gw * D4 + lane]   = hv;
    ((float4*)g_agg)[gw * D4 + lane] = make_float4(0.f, 0.f, 0.f, 0.f);
    __half2 h0 = __floats2half2_rn(hv.x, hv.y);
    __half2 h1 = __floats2half2_rn(hv.z, hv.w);
    uint2 packed;
    packed.x = *(unsigned int*)&h0;
    packed.y = *(unsigned int*)&h1;
    ((uint2*)g_h16)[gw * D4 + lane] = packed;
}

// fp16 copy of rel table (tiny)
__global__ void rel_convert_kernel(const float2* __restrict__ rel, int n2) {
    int i = blockIdx.x * blockDim.x + threadIdx.x;
    if (i >= n2) return;
    float2 v = rel[i];
    ((__half2*)g_rel16)[i] = __floats2half2_rn(v.x, v.y);
}

// ---------------- Phase B: edge gather (fp16) + scale + scatter-add (fp32) ----------------
__global__ void edge_kernel(const float* __restrict__ enorm,
                            const int*   __restrict__ src,
                            const int*   __restrict__ dst,
                            const int*   __restrict__ et,
                            int nE) {
    int gw   = (blockIdx.x * blockDim.x + threadIdx.x) >> 5;
    int lane = threadIdx.x & 31;
    const uint2* h16 = (const uint2*)g_h16;    // 8B = 4 halves per lane
    const uint2* r16 = (const uint2*)g_rel16;
    int e0 = gw * EPW;
#pragma unroll
    for (int i = 0; i < EPW; ++i) {
        int e = e0 + i;
        if (e < nE) {
            int   s  = __ldg(src + e);
            int   d  = __ldg(dst + e);
            int   t  = __ldg(et + e);
            float nm = __ldg(enorm + e);
            uint2 hp = h16[s * D4 + lane];
            uint2 rp = r16[t * D4 + lane];
            float2 h0 = __half22float2(*(__half2*)&hp.x);
            float2 h1 = __half22float2(*(__half2*)&hp.y);
            float2 r0 = __half22float2(*(__half2*)&rp.x);
            float2 r1 = __half22float2(*(__half2*)&rp.y);
            float4 v = make_float4((h0.x + r0.x) * nm, (h0.y + r0.y) * nm,
                                   (h1.x + r1.x) * nm, (h1.y + r1.y) * nm);
            float* p = g_agg + (d * D + lane * 4);
            asm volatile("red.global.add.v4.f32 [%0], {%1, %2, %3, %4};"
                         :: "l"(p), "f"(v.x), "f"(v.y), "f"(v.z), "f"(v.w)
                         : "memory");
        }
    }
}

// ---------------- Phase C (fused): both node GEMMs in one kernel ----------------
// Phase 1: hc = rrelu(agg @ Wn + h @ Ws)   -> fp16 tile in smem
// Phase 2: z  = hc @ Wt + bias ; gate = sigmoid(z)
// Epilogue: out = gate*hc + (1-gate)*his
__global__ __launch_bounds__(256, 2)
void fused_gemm_kernel(const float* __restrict__ Wn, const float* __restrict__ Ws,
                       const float* __restrict__ Wt, const float* __restrict__ bias,
                       const float* __restrict__ his, float* __restrict__ out, int M) {
    __shared__ float  As[8][132];
    __shared__ float  Bs[8][128];
    __shared__ __half Hc[128][132];   // h_cur tile, fp16 (33.8 KB)

    const int tid = threadIdx.x;
    const int m0  = blockIdx.x * 128;
    const int tx  = tid & 15;
    const int ty  = tid >> 4;

    float acc[8][8];
#pragma unroll
    for (int i = 0; i < 8; i++)
#pragma unroll
        for (int j = 0; j < 8; j++) acc[i][j] = 0.f;

    const int aRow = tid >> 1;
    const int aCol = (tid & 1) * 4;
    const int bRow = tid >> 5;
    const int bCol = (tid & 31) * 4;
    const bool aValid = (m0 + aRow) < M;

    // ---- Phase 1: K = 256 over [agg | h] x [Wn ; Ws] ----
#pragma unroll 1
    for (int seg = 0; seg < 2; ++seg) {
        const float* A = seg ? g_h : g_agg;
        const float* B = seg ? Ws : Wn;
#pragma unroll 1
        for (int k0 = 0; k0 < 128; k0 += 8) {
            float4 av = make_float4(0.f, 0.f, 0.f, 0.f);
            if (aValid) av = *(const float4*)(A + (m0 + aRow) * 128 + k0 + aCol);
            float4 bv = *(const float4*)(B + (k0 + bRow) * 128 + bCol);
            __syncthreads();
            As[aCol + 0][aRow] = av.x;
            As[aCol + 1][aRow] = av.y;
            As[aCol + 2][aRow] = av.z;
            As[aCol + 3][aRow] = av.w;
            *(float4*)(&Bs[bRow][bCol]) = bv;
            __syncthreads();
#pragma unroll
            for (int k = 0; k < 8; k++) {
                float a[8], b[8];
#pragma unroll
                for (int i = 0; i < 8; i++) a[i] = As[k][ty * 8 + i];
#pragma unroll
                for (int j = 0; j < 8; j++) b[j] = Bs[k][tx * 8 + j];
#pragma unroll
                for (int i = 0; i < 8; i++)
#pragma unroll
                    for (int j = 0; j < 8; j++)
                        acc[i][j] = fmaf(a[i], b[j], acc[i][j]);
            }
        }
    }

    // rrelu -> Hc (fp16)
    {
        const float SLOPE = 0.22916666666666666f;
        __half2* hc2 = (__half2*)&Hc[0][0];
        const int roww = 66;  // half2 per row (132/2)
#pragma unroll
        for (int i = 0; i < 8; i++) {
            int r = ty * 8 + i;
#pragma unroll
            for (int j = 0; j < 8; j += 2) {
                float c0 = acc[i][j];
                float c1 = acc[i][j + 1];
                c0 = (c0 >= 0.f) ? c0 : SLOPE * c0;
                c1 = (c1 >= 0.f) ? c1 : SLOPE * c1;
                hc2[r * roww + tx * 4 + (j >> 1)] = __floats2half2_rn(c0, c1);
            }
        }
    }

    // ---- Phase 2: K = 128 over Hc x Wt, A from smem ----
#pragma unroll
    for (int i = 0; i < 8; i++)
#pragma unroll
        for (int j = 0; j < 8; j++) acc[i][j] = 0.f;

    const __half2* hc2 = (const __half2*)&Hc[0][0];
    const int roww = 66;
#pragma unroll 1
    for (int k0 = 0; k0 < 128; k0 += 8) {
        float4 bv = *(const float4*)(Wt + (k0 + bRow) * 128 + bCol);
        __syncthreads();
        *(float4*)(&Bs[bRow][bCol]) = bv;
        __syncthreads();
#pragma unroll
        for (int kk = 0; kk < 8; kk += 2) {
            float2 a2[8];
#pragma unroll
            for (int i = 0; i < 8; i++)
                a2[i] = __half22float2(hc2[(ty * 8 + i) * roww + ((k0 + kk) >> 1)]);
            float b0[8], b1[8];
#pragma unroll
            for (int j = 0; j < 8; j++) { b0[j] = Bs[kk][tx * 8 + j]; b1[j] = Bs[kk + 1][tx * 8 + j]; }
#pragma unroll
            for (int i = 0; i < 8; i++)
#pragma unroll
                for (int j = 0; j < 8; j++) {
                    acc[i][j] = fmaf(a2[i].x, b0[j], acc[i][j]);
                    acc[i][j] = fmaf(a2[i].y, b1[j], acc[i][j]);
                }
        }
    }

    // ---- Epilogue: gate blend ----
    const int colb = tx * 8;
    float bj[8];
#pragma unroll
    for (int j = 0; j < 8; j++) bj[j] = bias[colb + j];
#pragma unroll
    for (int i = 0; i < 8; i++) {
        int r = m0 + ty * 8 + i;
        if (r >= M) continue;
        float hc[8];
#pragma unroll
        for (int j = 0; j < 8; j += 2) {
            float2 p = __half22float2(hc2[(ty * 8 + i) * roww + tx * 4 + (j >> 1)]);
            hc[j] = p.x; hc[j + 1] = p.y;
        }
        const float4* hi4 = (const float4*)(his + r * 128 + colb);
        float4 hiA = hi4[0], hiB = hi4[1];
        float hi[8] = {hiA.x, hiA.y, hiA.z, hiA.w, hiB.x, hiB.y, hiB.z, hiB.w};
        float v[8];
#pragma unroll
        for (int j = 0; j < 8; j++) {
            float z = acc[i][j] + bj[j];
            float g = 1.f / (1.f + __expf(-z));
            v[j] = g * hc[j] + (1.f - g) * hi[j];
        }
        float4* o = (float4*)(out + r * 128 + colb);
        o[0] = make_float4(v[0], v[1], v[2], v[3]);
        o[1] = make_float4(v[4], v[5], v[6], v[7]);
    }
}

extern "C" void kernel_launch(void* const* d_in, const int* in_sizes, int n_in,
                              void* d_out, int out_size) {
    const float* ent = (const float*)d_in[0];
    const float* rel = (const float*)d_in[1];
    const float* his = (const float*)d_in[2];
    const float* Wn  = (const float*)d_in[3];
    const float* Ws  = (const float*)d_in[4];
    const float* Wt  = (const float*)d_in[5];
    const float* tb  = (const float*)d_in[6];
    const float* en  = (const float*)d_in[7];
    const int*   src = (const int*)d_in[8];
    const int*   dst = (const int*)d_in[9];
    const int*   et  = (const int*)d_in[10];

    int M   = in_sizes[0] / D;   // 100000
    int E   = in_sizes[7];       // 2000000
    int nR2 = in_sizes[1] / 2;   // rel elems / 2

    // Phase A: normalize + zero agg + fp16 copies
    int nblocks = (M + 7) / 8;
    norm_zero_kernel<<<nblocks, 256>>>((const float4*)ent, M);
    rel_convert_kernel<<<(nR2 + 255) / 256, 256>>>((const float2*)rel, nR2);

    // Phase B: edges
    int ewarps  = (E + EPW - 1) / EPW;
    int eblocks = (ewarps + 7) / 8;
    edge_kernel<<<eblocks, 256>>>(en, src, dst, et, E);

    // Phase C: fused node GEMMs + epilogue
    int gblocks = (M + 127) / 128;
    fused_gemm_kernel<<<gblocks, 256>>>(Wn, Ws, Wt, tb, his, (float*)d_out, M);
}

// round 4
// speedup vs baseline: 1.0491x; 1.0289x over previous
#include <cuda_runtime.h>
#include <cuda_fp16.h>
#include <math.h>

#define D      128
#define D4     32
#define NE_MAX 100000
#define NREL   1000
#define EPW    4

// Scratch (no allocation allowed)
__device__ float  g_agg[NE_MAX * D];      // 51.2 MB fp32 accumulator
__device__ __half g_h16[NE_MAX * D];      // 25.6 MB fp16 normalized h
__device__ __half g_rel16[NREL * D];      // 256 KB fp16 rel table

// ---------- helpers ----------
static __device__ __forceinline__ unsigned short f2h(float x) {
    unsigned short u;
    asm("cvt.rn.f16.f32 %0, %1;" : "=h"(u) : "f"(x));
    return u;
}
static __device__ __forceinline__ unsigned int packh(float lo, float hi) {
    unsigned int r;
    asm("cvt.rn.f16x2.f32 %0, %1, %2;" : "=r"(r) : "f"(hi), "f"(lo));
    return r;
}
static __device__ __forceinline__ void mma16816(float c[4], const unsigned int a[4],
                                                const unsigned int b[2]) {
    asm volatile(
        "mma.sync.aligned.m16n8k16.row.col.f32.f16.f16.f32 "
        "{%0,%1,%2,%3}, {%4,%5,%6,%7}, {%8,%9}, {%0,%1,%2,%3};"
        : "+f"(c[0]), "+f"(c[1]), "+f"(c[2]), "+f"(c[3])
        : "r"(a[0]), "r"(a[1]), "r"(a[2]), "r"(a[3]), "r"(b[0]), "r"(b[1]));
}

// ---------------- Phase A: L2-normalize -> fp16, zero accumulator ----------------
__global__ void norm_zero_kernel(const float4* __restrict__ ent, int rows) {
    int gw   = (blockIdx.x * blockDim.x + threadIdx.x) >> 5;
    int lane = threadIdx.x & 31;
    if (gw >= rows) return;
    float4 v = ent[gw * D4 + lane];
    float  s = v.x * v.x + v.y * v.y + v.z * v.z + v.w * v.w;
#pragma unroll
    for (int o = 16; o > 0; o >>= 1) s += __shfl_xor_sync(0xffffffffu, s, o);
    float inv = 1.0f / fmaxf(sqrtf(s), 1e-12f);
    ((float4*)g_agg)[gw * D4 + lane] = make_float4(0.f, 0.f, 0.f, 0.f);
    uint2 packed;
    packed.x = packh(v.x * inv, v.y * inv);
    packed.y = packh(v.z * inv, v.w * inv);
    ((uint2*)g_h16)[gw * D4 + lane] = packed;
}

__global__ void rel_convert_kernel(const float2* __restrict__ rel, int n2) {
    int i = blockIdx.x * blockDim.x + threadIdx.x;
    if (i >= n2) return;
    float2 v = rel[i];
    ((unsigned int*)g_rel16)[i] = packh(v.x, v.y);
}

// ---------------- Phase B: edge gather (fp16) + scale + scatter-add (fp32) ----------------
__global__ void edge_kernel(const float* __restrict__ enorm,
                            const int*   __restrict__ src,
                            const int*   __restrict__ dst,
                            const int*   __restrict__ et,
                            int nE) {
    int gw   = (blockIdx.x * blockDim.x + threadIdx.x) >> 5;
    int lane = threadIdx.x & 31;
    const uint2* h16 = (const uint2*)g_h16;
    const uint2* r16 = (const uint2*)g_rel16;
    int e0 = gw * EPW;
#pragma unroll
    for (int i = 0; i < EPW; ++i) {
        int e = e0 + i;
        if (e < nE) {
            int   s  = __ldg(src + e);
            int   d  = __ldg(dst + e);
            int   t  = __ldg(et + e);
            float nm = __ldg(enorm + e);
            uint2 hp = h16[s * D4 + lane];
            uint2 rp = r16[t * D4 + lane];
            float2 h0 = __half22float2(*(__half2*)&hp.x);
            float2 h1 = __half22float2(*(__half2*)&hp.y);
            float2 r0 = __half22float2(*(__half2*)&rp.x);
            float2 r1 = __half22float2(*(__half2*)&rp.y);
            float4 v = make_float4((h0.x + r0.x) * nm, (h0.y + r0.y) * nm,
                                   (h1.x + r1.x) * nm, (h1.y + r1.y) * nm);
            float* p = g_agg + (d * D + lane * 4);
            asm volatile("red.global.add.v4.f32 [%0], {%1, %2, %3, %4};"
                         :: "l"(p), "f"(v.x), "f"(v.y), "f"(v.z), "f"(v.w)
                         : "memory");
        }
    }
}

// ---------------- Phase C (fused, tensor-core): both node GEMMs ----------------
// Phase 1: hc = rrelu(agg @ Wn + h @ Ws)  (fp16 MMA, fp32 accum) -> Hc smem fp16
// Phase 2: z  = hc @ Wt + bias ; gate = sigmoid(z)
// Epilogue: out = gate*hc + (1-gate)*his
#define AS_S 18     // A/B smem stride in halves (16 + 2 pad)
#define HC_S 136    // Hc smem stride in halves (128 + 8 pad)

__global__ __launch_bounds__(256)
void fused_mma_kernel(const float* __restrict__ Wn, const float* __restrict__ Ws,
                      const float* __restrict__ Wt, const float* __restrict__ bias,
                      const float* __restrict__ his, float* __restrict__ out, int M) {
    __shared__ __align__(16) unsigned short As[128 * AS_S];
    __shared__ __align__(16) unsigned short Bs[128 * AS_S];
    __shared__ __align__(16) unsigned short Hc[128 * HC_S];

    const int tid  = threadIdx.x;
    const int lane = tid & 31;
    const int wid  = tid >> 5;
    const int wm   = wid >> 1;          // 0..3  (row block of 32)
    const int wn   = wid & 1;           // 0..1  (col block of 64)
    const int m0   = blockIdx.x * 128;

    const int r  = lane >> 2;           // 0..7
    const int cq = (lane & 3) * 2;      // 0,2,4,6

    float acc[2][8][4];
#pragma unroll
    for (int mt = 0; mt < 2; mt++)
#pragma unroll
        for (int nf = 0; nf < 8; nf++)
#pragma unroll
            for (int k = 0; k < 4; k++) acc[mt][nf][k] = 0.f;

    // ================= Phase 1: K = 256 over [agg | h16] x [Wn ; Ws] =================
#pragma unroll 1
    for (int seg = 0; seg < 2; ++seg) {
        const float* Bw = seg ? Ws : Wn;
#pragma unroll 1
        for (int k0 = 0; k0 < 128; k0 += 16) {
            // --- stage A chunk (128 x 16 fp16) ---
            if (seg == 0) {
#pragma unroll
                for (int it = 0; it < 2; ++it) {
                    int f = tid + it * 256;
                    int row = f >> 2, cw = f & 3;
                    unsigned int p0 = 0, p1 = 0;
                    if (m0 + row < M) {
                        float4 v = *(const float4*)(g_agg + (size_t)(m0 + row) * 128 + k0 + cw * 4);
                        p0 = packh(v.x, v.y);
                        p1 = packh(v.z, v.w);
                    }
                    unsigned int* dst = (unsigned int*)&As[row * AS_S + cw * 4];
                    dst[0] = p0; dst[1] = p1;
                }
            } else {
#pragma unroll
                for (int it = 0; it < 2; ++it) {
                    int f = tid + it * 256;
                    int row = f >> 2, cw = f & 3;
                    uint2 p = make_uint2(0u, 0u);
                    if (m0 + row < M)
                        p = ((const uint2*)g_h16)[(size_t)(m0 + row) * 32 + (k0 >> 2) + cw];
                    unsigned int* dst = (unsigned int*)&As[row * AS_S + cw * 4];
                    dst[0] = p.x; dst[1] = p.y;
                }
            }
            // --- stage B chunk transposed (Bs[n][k], fp16) ---
#pragma unroll
            for (int it = 0; it < 2; ++it) {
                int f = tid + it * 256;
                int kr = f >> 5, n0 = (f & 31) * 4;
                float4 v = *(const float4*)(Bw + (size_t)(k0 + kr) * 128 + n0);
                Bs[(n0 + 0) * AS_S + kr] = f2h(v.x);
                Bs[(n0 + 1) * AS_S + kr] = f2h(v.y);
                Bs[(n0 + 2) * AS_S + kr] = f2h(v.z);
                Bs[(n0 + 3) * AS_S + kr] = f2h(v.w);
            }
            __syncthreads();
            // --- fragments + MMA ---
            unsigned int a[2][4], b[8][2];
#pragma unroll
            for (int mt = 0; mt < 2; mt++) {
                int base = wm * 32 + mt * 16;
                a[mt][0] = *(const unsigned int*)&As[(base + r) * AS_S + cq];
                a[mt][1] = *(const unsigned int*)&As[(base + r + 8) * AS_S + cq];
                a[mt][2] = *(const unsigned int*)&As[(base + r) * AS_S + cq + 8];
                a[mt][3] = *(const unsigned int*)&As[(base + r + 8) * AS_S + cq + 8];
            }
#pragma unroll
            for (int nf = 0; nf < 8; nf++) {
                int n = wn * 64 + nf * 8 + r;
                b[nf][0] = *(const unsigned int*)&Bs[n * AS_S + cq];
                b[nf][1] = *(const unsigned int*)&Bs[n * AS_S + cq + 8];
            }
#pragma unroll
            for (int mt = 0; mt < 2; mt++)
#pragma unroll
                for (int nf = 0; nf < 8; nf++)
                    mma16816(acc[mt][nf], a[mt], b[nf]);
            __syncthreads();
        }
    }

    // ---- rrelu -> Hc (fp16, A-fragment-compatible layout) ----
    {
        const float SLOPE = 0.22916666666666666f;
#pragma unroll
        for (int mt = 0; mt < 2; mt++) {
            int r1 = wm * 32 + mt * 16 + r;
#pragma unroll
            for (int nf = 0; nf < 8; nf++) {
                int col = wn * 64 + nf * 8 + cq;
                float c0 = acc[mt][nf][0], c1 = acc[mt][nf][1];
                float c2 = acc[mt][nf][2], c3 = acc[mt][nf][3];
                c0 = (c0 >= 0.f) ? c0 : SLOPE * c0;
                c1 = (c1 >= 0.f) ? c1 : SLOPE * c1;
                c2 = (c2 >= 0.f) ? c2 : SLOPE * c2;
                c3 = (c3 >= 0.f) ? c3 : SLOPE * c3;
                *(unsigned int*)&Hc[r1 * HC_S + col]       = packh(c0, c1);
                *(unsigned int*)&Hc[(r1 + 8) * HC_S + col] = packh(c2, c3);
            }
        }
    }
#pragma unroll
    for (int mt = 0; mt < 2; mt++)
#pragma unroll
        for (int nf = 0; nf < 8; nf++)
#pragma unroll
            for (int k = 0; k < 4; k++) acc[mt][nf][k] = 0.f;

    // ================= Phase 2: K = 128 over Hc x Wt (A from smem) =================
#pragma unroll 1
    for (int k0 = 0; k0 < 128; k0 += 16) {
#pragma unroll
        for (int it = 0; it < 2; ++it) {
            int f = tid + it * 256;
            int kr = f >> 5, n0 = (f & 31) * 4;
            float4 v = *(const float4*)(Wt + (size_t)(k0 + kr) * 128 + n0);
            Bs[(n0 + 0) * AS_S + kr] = f2h(v.x);
            Bs[(n0 + 1) * AS_S + kr] = f2h(v.y);
            Bs[(n0 + 2) * AS_S + kr] = f2h(v.z);
            Bs[(n0 + 3) * AS_S + kr] = f2h(v.w);
        }
        __syncthreads();
        unsigned int a[2][4], b[8][2];
#pragma unroll
        for (int mt = 0; mt < 2; mt++) {
            int base = wm * 32 + mt * 16;
            a[mt][0] = *(const unsigned int*)&Hc[(base + r) * HC_S + k0 + cq];
            a[mt][1] = *(const unsigned int*)&Hc[(base + r + 8) * HC_S + k0 + cq];
            a[mt][2] = *(const unsigned int*)&Hc[(base + r) * HC_S + k0 + cq + 8];
            a[mt][3] = *(const unsigned int*)&Hc[(base + r + 8) * HC_S + k0 + cq + 8];
        }
#pragma unroll
        for (int nf = 0; nf < 8; nf++) {
            int n = wn * 64 + nf * 8 + r;
            b[nf][0] = *(const unsigned int*)&Bs[n * AS_S + cq];
            b[nf][1] = *(const unsigned int*)&Bs[n * AS_S + cq + 8];
        }
#pragma unroll
        for (int mt = 0; mt < 2; mt++)
#pragma unroll
            for (int nf = 0; nf < 8; nf++)
                mma16816(acc[mt][nf], a[mt], b[nf]);
        __syncthreads();
    }

    // ---- Epilogue: gate blend ----
#pragma unroll
    for (int mt = 0; mt < 2; mt++) {
        int lr1 = wm * 32 + mt * 16 + r;     // local rows
        int lr2 = lr1 + 8;
#pragma unroll
        for (int nf = 0; nf < 8; nf++) {
            int col = wn * 64 + nf * 8 + cq;
            float b0 = __ldg(bias + col), b1 = __ldg(bias + col + 1);
#pragma unroll
            for (int half = 0; half < 2; half++) {
                int lr  = half ? lr2 : lr1;
                int row = m0 + lr;
                if (row >= M) continue;
                float z0 = acc[mt][nf][half * 2 + 0] + b0;
                float z1 = acc[mt][nf][half * 2 + 1] + b1;
                float g0 = 1.f / (1.f + __expf(-z0));
                float g1 = 1.f / (1.f + __expf(-z1));
                unsigned int hcp = *(const unsigned int*)&Hc[lr * HC_S + col];
                float2 hc = __half22float2(*(__half2*)&hcp);
                float2 hi = *(const float2*)(his + (size_t)row * 128 + col);
                float2 o;
                o.x = g0 * hc.x + (1.f - g0) * hi.x;
                o.y = g1 * hc.y + (1.f - g1) * hi.y;
                *(float2*)(out + (size_t)row * 128 + col) = o;
            }
        }
    }
}

extern "C" void kernel_launch(void* const* d_in, const int* in_sizes, int n_in,
                              void* d_out, int out_size) {
    const float* ent = (const float*)d_in[0];
    const float* rel = (const float*)d_in[1];
    const float* his = (const float*)d_in[2];
    const float* Wn  = (const float*)d_in[3];
    const float* Ws  = (const float*)d_in[4];
    const float* Wt  = (const float*)d_in[5];
    const float* tb  = (const float*)d_in[6];
    const float* en  = (const float*)d_in[7];
    const int*   src = (const int*)d_in[8];
    const int*   dst = (const int*)d_in[9];
    const int*   et  = (const int*)d_in[10];

    int M   = in_sizes[0] / D;   // 100000
    int E   = in_sizes[7];       // 2000000
    int nR2 = in_sizes[1] / 2;

    int nblocks = (M + 7) / 8;
    norm_zero_kernel<<<nblocks, 256>>>((const float4*)ent, M);
    rel_convert_kernel<<<(nR2 + 255) / 256, 256>>>((const float2*)rel, nR2);

    int ewarps  = (E + EPW - 1) / EPW;
    int eblocks = (ewarps + 7) / 8;
    edge_kernel<<<eblocks, 256>>>(en, src, dst, et, E);

    int gblocks = (M + 127) / 128;
    fused_mma_kernel<<<gblocks, 256>>>(Wn, Ws, Wt, tb, his, (float*)d_out, M);
}